// round 16
// baseline (speedup 1.0000x reference)
#include <cuda_runtime.h>
#include <math.h>
#include <stdint.h>

// ---------------- problem constants ----------------
#define NNODES 50000
#define NEDGES 600000
#define NDISC  70
#define NH     64
#define EMB    128
#define DDIM   192
#define RESHID 512
#define PREDH  320
#define ZDIM   384
#define NBLK   49

// ---------------- device scratch ----------------
__device__ float g_dinv [NNODES];
__device__ float g_x    [NNODES * DDIM];
__device__ float g_xg   [NNODES * EMB];
__device__ float g_h    [NNODES * RESHID];
__device__ float g_xdeep[NNODES * DDIM];
__device__ float g_z    [NNODES * ZDIM];
__device__ int   g_indeg [NNODES];
__device__ int   g_cursor[NNODES];
__device__ int   g_rowptr[NNODES + 1];
__device__ int   g_srcrow[NEDGES];
__device__ int   g_blksum[64];
__device__ int   g_blkoff[64];

#define BUF_NONE  0
#define BUF_X     1
#define BUF_XG    2
#define BUF_H     3
#define BUF_XDEEP 4
#define BUF_Z     5

__device__ __forceinline__ float* bufptr(int id) {
    switch (id) {
        case BUF_X:     return g_x;
        case BUF_XG:    return g_xg;
        case BUF_H:     return g_h;
        case BUF_XDEEP: return g_xdeep;
        case BUF_Z:     return g_z;
        default:        return nullptr;
    }
}

__device__ __forceinline__ float leakyf(float v) { return v > 0.0f ? v : 0.01f * v; }

__device__ __forceinline__ uint32_t to_tf32(float f) {
    uint32_t r; asm("cvt.rna.tf32.f32 %0, %1;" : "=r"(r) : "f"(f)); return r;
}
__device__ __forceinline__ void split_tf32(float v, uint32_t& hi, uint32_t& lo) {
    hi = to_tf32(v);
    lo = to_tf32(v - __uint_as_float(hi));
}

__device__ __forceinline__ void mma_tf32(float* c, const uint32_t* a, const uint32_t* b) {
    asm volatile(
        "mma.sync.aligned.m16n8k8.row.col.f32.tf32.tf32.f32 "
        "{%0,%1,%2,%3}, {%4,%5,%6,%7}, {%8,%9}, {%0,%1,%2,%3};"
        : "+f"(c[0]), "+f"(c[1]), "+f"(c[2]), "+f"(c[3])
        : "r"(a[0]), "r"(a[1]), "r"(a[2]), "r"(a[3]), "r"(b[0]), "r"(b[1]));
}

__device__ __forceinline__ uint32_t smem_u32(const void* p) {
    uint32_t a;
    asm("{ .reg .u64 t; cvta.to.shared.u64 t, %1; cvt.u32.u64 %0, t; }" : "=r"(a) : "l"(p));
    return a;
}
__device__ __forceinline__ void cp16(uint32_t dst, const void* src, int sz) {
    asm volatile("cp.async.ca.shared.global [%0], [%1], 16, %2;"
                 :: "r"(dst), "l"(src), "r"(sz) : "memory");
}
#define CP_COMMIT() asm volatile("cp.async.commit_group;" ::: "memory")
#define CP_WAIT0()  asm volatile("cp.async.wait_group 0;" ::: "memory")

// ---------------- graph prep ----------------
__global__ void k_zero_int() {
    int i = blockIdx.x * blockDim.x + threadIdx.x;
    if (i < NNODES) { g_indeg[i] = 0; g_cursor[i] = 0; }
}
__global__ void k_count(const int* __restrict__ col) {
    int e = blockIdx.x * blockDim.x + threadIdx.x;
    if (e < NEDGES) atomicAdd(&g_indeg[col[e]], 1);
}
__global__ void k_dinv() {
    int i = blockIdx.x * blockDim.x + threadIdx.x;
    if (i < NNODES) g_dinv[i] = rsqrtf((float)g_indeg[i] + 1.0f);
}
__global__ void __launch_bounds__(1024) k_scan1() {
    __shared__ int sh[32];
    int i = blockIdx.x * 1024 + threadIdx.x;
    int v = (i < NNODES) ? g_indeg[i] : 0;
    #pragma unroll
    for (int o = 16; o; o >>= 1) v += __shfl_xor_sync(~0u, v, o);
    if ((threadIdx.x & 31) == 0) sh[threadIdx.x >> 5] = v;
    __syncthreads();
    if (threadIdx.x < 32) {
        int t = sh[threadIdx.x];
        #pragma unroll
        for (int o = 16; o; o >>= 1) t += __shfl_xor_sync(~0u, t, o);
        if (threadIdx.x == 0) g_blksum[blockIdx.x] = t;
    }
}
__global__ void k_scan2() {
    if (threadIdx.x == 0) {
        int run = 0;
        for (int b = 0; b < NBLK; b++) { g_blkoff[b] = run; run += g_blksum[b]; }
        g_rowptr[NNODES] = run;
    }
}
__global__ void __launch_bounds__(1024) k_scan3() {
    __shared__ int wsum[32];
    int i = blockIdx.x * 1024 + threadIdx.x;
    int lane = threadIdx.x & 31, w = threadIdx.x >> 5;
    int v = (i < NNODES) ? g_indeg[i] : 0;
    int s = v;
    #pragma unroll
    for (int o = 1; o < 32; o <<= 1) {
        int t = __shfl_up_sync(~0u, s, o);
        if (lane >= o) s += t;
    }
    if (lane == 31) wsum[w] = s;
    __syncthreads();
    if (w == 0) {
        int t = wsum[lane];
        #pragma unroll
        for (int o = 1; o < 32; o <<= 1) {
            int u = __shfl_up_sync(~0u, t, o);
            if (lane >= o) t += u;
        }
        wsum[lane] = t;
    }
    __syncthreads();
    if (i < NNODES)
        g_rowptr[i] = s - v + (w > 0 ? wsum[w - 1] : 0) + g_blkoff[blockIdx.x];
}
__global__ void k_fill(const int* __restrict__ rows, const int* __restrict__ cols) {
    int e = blockIdx.x * blockDim.x + threadIdx.x;
    if (e < NEDGES) {
        int c = cols[e];
        int pos = g_rowptr[c] + atomicAdd(&g_cursor[c], 1);
        g_srcrow[pos] = rows[e];
    }
}

__global__ void k_cast(const int* __restrict__ disc) {
    int i = blockIdx.x * blockDim.x + threadIdx.x;
    if (i < NNODES * NH) {
        int m = i >> 6, c = i & 63;
        g_x[(size_t)m * DDIM + c] = (float)disc[(size_t)m * NDISC + c];
    }
}

// ---------------- fused GCN aggregate ----------------
__global__ void k_gather(const float* __restrict__ bias,
                         int dst_id, int dst_ld, int dst_off) {
    int node = (blockIdx.x * blockDim.x + threadIdx.x) >> 5;
    int lane = threadIdx.x & 31;
    if (node >= NNODES) return;
    float dc = g_dinv[node];
    int s = g_rowptr[node], e = g_rowptr[node + 1];
    float4 sum = make_float4(0.f, 0.f, 0.f, 0.f);
    for (int i = s; i < e; i++) {
        int r = g_srcrow[i];
        float nrm = g_dinv[r] * dc;
        float4 v = *(const float4*)(g_h + (size_t)r * EMB + lane * 4);
        sum.x = fmaf(v.x, nrm, sum.x);
        sum.y = fmaf(v.y, nrm, sum.y);
        sum.z = fmaf(v.z, nrm, sum.z);
        sum.w = fmaf(v.w, nrm, sum.w);
    }
    float4 hv = *(const float4*)(g_h + (size_t)node * EMB + lane * 4);
    float4 b4 = *(const float4*)(bias + lane * 4);
    float d2 = dc * dc;
    sum.x = leakyf(fmaf(hv.x, d2, sum.x) + b4.x);
    sum.y = leakyf(fmaf(hv.y, d2, sum.y) + b4.y);
    sum.z = leakyf(fmaf(hv.z, d2, sum.z) + b4.z);
    sum.w = leakyf(fmaf(hv.w, d2, sum.w) + b4.w);
    *(float4*)(bufptr(dst_id) + (size_t)node * dst_ld + dst_off + lane * 4) = sum;
}

// ---------------- 3xTF32 mma.sync GEMM (cp.async 2-stage, raw fp32 smem, 3 CTAs/SM) ----------------
#define AS_LD 36
#define BS_LD 72
#define A_TILE (128 * AS_LD)             // 4608 floats
#define B_TILE (32 * BS_LD)              // 2304 floats
#define STAGE_U32 (A_TILE + B_TILE)      // 6912 floats = 27648 B
#define SMEM_BYTES (2 * STAGE_U32 * 4)   // 55296 B

__global__ void __launch_bounds__(256, 3) k_gemm_mma(
    int a_id, int lda,
    const float* __restrict__ W,
    const float* __restrict__ bias,
    int c_id, int ldc,
    int r_id, int ldr,
    int M, int N, int K, int act)
{
    extern __shared__ __align__(16) float sm[];
    uint32_t sb = smem_u32(sm);

    const float* A = bufptr(a_id);
    float* C = bufptr(c_id);
    const float* R = bufptr(r_id);

    int tid = threadIdx.x;
    int wid = tid >> 5, lane = tid & 31;
    int gid = lane >> 2, tig = lane & 3;
    int wm = wid & 3, wn = wid >> 2;

    int n0 = blockIdx.x * 64;
    int m0 = blockIdx.y * 128;

    int a_row[4], a_kg[4];
    #pragma unroll
    for (int p = 0; p < 4; p++) {
        int g = tid + p * 256;
        a_row[p] = g >> 3;
        a_kg[p]  = g & 7;
    }
    int b_row[2], b_ng[2];
    #pragma unroll
    for (int p = 0; p < 2; p++) {
        int g = tid + p * 256;
        b_row[p] = g >> 4;
        b_ng[p]  = g & 15;
    }

    float acc[2][4][4] = {};
    int nchunks = K >> 5;

    // issue chunk 0 into stage 0
    {
        uint32_t abase = sb;
        uint32_t bbase = sb + A_TILE * 4;
        #pragma unroll
        for (int p = 0; p < 4; p++) {
            int row = a_row[p];
            const float* src = A + (size_t)(m0 + row) * lda + a_kg[p] * 4;
            int sz = (m0 + row < M) ? 16 : 0;
            if (!sz) src = A;
            cp16(abase + (uint32_t)(row * AS_LD + a_kg[p] * 4) * 4, src, sz);
        }
        #pragma unroll
        for (int p = 0; p < 2; p++) {
            const float* src = W + (size_t)b_row[p] * N + n0 + b_ng[p] * 4;
            cp16(bbase + (uint32_t)(b_row[p] * BS_LD + b_ng[p] * 4) * 4, src, 16);
        }
        CP_COMMIT();
    }

    for (int kc = 0; kc < nchunks; kc++) {
        CP_WAIT0();
        __syncthreads();

        if (kc + 1 < nchunks) {
            int k0n = (kc + 1) << 5;
            uint32_t stg = sb + (uint32_t)(((kc + 1) & 1) * STAGE_U32) * 4;
            uint32_t abase = stg;
            uint32_t bbase = stg + A_TILE * 4;
            #pragma unroll
            for (int p = 0; p < 4; p++) {
                int row = a_row[p];
                const float* src = A + (size_t)(m0 + row) * lda + k0n + a_kg[p] * 4;
                int sz = (m0 + row < M) ? 16 : 0;
                if (!sz) src = A;
                cp16(abase + (uint32_t)(row * AS_LD + a_kg[p] * 4) * 4, src, sz);
            }
            #pragma unroll
            for (int p = 0; p < 2; p++) {
                const float* src = W + (size_t)(k0n + b_row[p]) * N + n0 + b_ng[p] * 4;
                cp16(bbase + (uint32_t)(b_row[p] * BS_LD + b_ng[p] * 4) * 4, src, 16);
            }
            CP_COMMIT();
        }

        const float* As = sm + (kc & 1) * STAGE_U32;
        const float* Bs = As + A_TILE;
        #pragma unroll
        for (int ks = 0; ks < 4; ks++) {
            int kl = ks * 8;
            uint32_t ah[2][4], al[2][4];
            #pragma unroll
            for (int mt = 0; mt < 2; mt++) {
                int row = wm * 32 + mt * 16 + gid;
                float r0 = As[(row    ) * AS_LD + kl + tig    ];
                float r1 = As[(row + 8) * AS_LD + kl + tig    ];
                float r2 = As[(row    ) * AS_LD + kl + tig + 4];
                float r3 = As[(row + 8) * AS_LD + kl + tig + 4];
                split_tf32(r0, ah[mt][0], al[mt][0]);
                split_tf32(r1, ah[mt][1], al[mt][1]);
                split_tf32(r2, ah[mt][2], al[mt][2]);
                split_tf32(r3, ah[mt][3], al[mt][3]);
            }
            #pragma unroll
            for (int nt = 0; nt < 4; nt++) {
                int ncol = wn * 32 + nt * 8 + gid;
                float q0 = Bs[(kl + tig    ) * BS_LD + ncol];
                float q1 = Bs[(kl + tig + 4) * BS_LD + ncol];
                uint32_t bh[2], bl[2];
                split_tf32(q0, bh[0], bl[0]);
                split_tf32(q1, bh[1], bl[1]);
                #pragma unroll
                for (int mt = 0; mt < 2; mt++) {
                    mma_tf32(acc[mt][nt], al[mt], bh);
                    mma_tf32(acc[mt][nt], ah[mt], bl);
                    mma_tf32(acc[mt][nt], ah[mt], bh);
                }
            }
        }
        __syncthreads();
    }

    #pragma unroll
    for (int mt = 0; mt < 2; mt++) {
        int row0 = m0 + wm * 32 + mt * 16 + gid;
        #pragma unroll
        for (int nt = 0; nt < 4; nt++) {
            int n = n0 + wn * 32 + nt * 8 + 2 * tig;
            float b0 = 0.f, b1 = 0.f;
            if (bias) { b0 = bias[n]; b1 = bias[n + 1]; }
            #pragma unroll
            for (int half = 0; half < 2; half++) {
                int m = row0 + half * 8;
                if (m < M) {
                    float v0 = acc[mt][nt][half * 2 + 0] + b0;
                    float v1 = acc[mt][nt][half * 2 + 1] + b1;
                    if (R) {
                        v0 += R[(size_t)m * ldr + n];
                        v1 += R[(size_t)m * ldr + n + 1];
                    }
                    if (act) { v0 = leakyf(v0); v1 = leakyf(v1); }
                    *(float2*)(C + (size_t)m * ldc + n) = make_float2(v0, v1);
                }
            }
        }
    }
}

// ---------------- CrossNet ----------------
__global__ void k_cross(const float* __restrict__ cw, const float* __restrict__ cb) {
    int warp = (blockIdx.x * blockDim.x + threadIdx.x) >> 5;
    int lane = threadIdx.x & 31;
    if (warp >= NNODES) return;
    float x0[6], xc[6];
    #pragma unroll
    for (int j = 0; j < 6; j++) {
        x0[j] = g_x[(size_t)warp * DDIM + lane + 32 * j];
        xc[j] = x0[j];
    }
    #pragma unroll
    for (int l = 0; l < 2; l++) {
        float p = 0.0f;
        #pragma unroll
        for (int j = 0; j < 6; j++)
            p = fmaf(xc[j], cw[l * DDIM + lane + 32 * j], p);
        #pragma unroll
        for (int o = 16; o > 0; o >>= 1)
            p += __shfl_xor_sync(0xffffffffu, p, o);
        float xw = p;
        #pragma unroll
        for (int j = 0; j < 6; j++)
            xc[j] = fmaf(x0[j], xw, cb[l * DDIM + lane + 32 * j] + xc[j]);
    }
    #pragma unroll
    for (int j = 0; j < 6; j++)
        g_z[(size_t)warp * ZDIM + DDIM + lane + 32 * j] = xc[j];
}

// ---------------- final GEMV + sigmoid ----------------
__global__ void k_pred2(const float* __restrict__ w, const float* __restrict__ b,
                        float* __restrict__ out) {
    int warp = (blockIdx.x * blockDim.x + threadIdx.x) >> 5;
    int lane = threadIdx.x & 31;
    if (warp >= NNODES) return;
    float p = 0.0f;
    #pragma unroll
    for (int j = 0; j < 10; j++) {
        int c = lane + 32 * j;
        p = fmaf(g_h[(size_t)warp * PREDH + c], w[c], p);
    }
    #pragma unroll
    for (int o = 16; o > 0; o >>= 1)
        p += __shfl_xor_sync(0xffffffffu, p, o);
    if (lane == 0) {
        float v = p + b[0];
        out[warp] = 1.0f / (1.0f + expf(-v));
    }
}

// ---------------- launch (multi-stream fork/join) ----------------
extern "C" void kernel_launch(void* const* d_in, const int* in_sizes, int n_in,
                              void* d_out, int out_size) {
    const int* disc  = (const int*)d_in[0];
    const int* erow  = (const int*)d_in[1];
    const int* ecol  = erow + NEDGES;
    const float* w_g0   = (const float*)d_in[2];
    const float* b_g0   = (const float*)d_in[3];
    const float* w_gcn1 = (const float*)d_in[4];
    const float* b_gcn1 = (const float*)d_in[5];
    const float* w_gcn2 = (const float*)d_in[6];
    const float* b_gcn2 = (const float*)d_in[7];
    const float* res_w1 = (const float*)d_in[8];
    const float* res_b1 = (const float*)d_in[9];
    const float* res_w2 = (const float*)d_in[10];
    const float* res_b2 = (const float*)d_in[11];
    const float* cross_w = (const float*)d_in[12];
    const float* cross_b = (const float*)d_in[13];
    const float* p_w1 = (const float*)d_in[14];
    const float* p_b1 = (const float*)d_in[15];
    const float* p_w2 = (const float*)d_in[16];
    const float* p_b2 = (const float*)d_in[17];
    float* out = (float*)d_out;

    const int T = 256;
    const int MB = (NNODES + 127) / 128;   // 391
    const int SMB = SMEM_BYTES;            // 55296

    static int inited = 0;
    static cudaStream_t s2;
    static cudaEvent_t evA, evB, evC, evD;
    if (!inited) {
        cudaFuncSetAttribute(k_gemm_mma, cudaFuncAttributeMaxDynamicSharedMemorySize, SMB);
        cudaStreamCreateWithFlags(&s2, cudaStreamNonBlocking);
        cudaEventCreateWithFlags(&evA, cudaEventDisableTiming);
        cudaEventCreateWithFlags(&evB, cudaEventDisableTiming);
        cudaEventCreateWithFlags(&evC, cudaEventDisableTiming);
        cudaEventCreateWithFlags(&evD, cudaEventDisableTiming);
        inited = 1;
    }

    // ---- main stream: cast feeds the embed GEMM directly (raw weights)
    k_cast<<<(NNODES*NH + T-1)/T, T>>>(disc);

    // ---- fork: graph prep on s2, overlapped with embed + gcn1-linear GEMMs
    cudaEventRecord(evA, 0);
    cudaStreamWaitEvent(s2, evA, 0);
    k_zero_int<<<(NNODES + T-1)/T, T, 0, s2>>>();
    k_count<<<(NEDGES + T-1)/T, T, 0, s2>>>(ecol);
    k_dinv<<<(NNODES + T-1)/T, T, 0, s2>>>();
    k_scan1<<<NBLK, 1024, 0, s2>>>();
    k_scan2<<<1, 32, 0, s2>>>();
    k_scan3<<<NBLK, 1024, 0, s2>>>();
    k_fill<<<(NEDGES + T-1)/T, T, 0, s2>>>(erow, ecol);
    cudaEventRecord(evB, s2);

    // embed: xg = leaky(x_d @ w_g0 + b)
    k_gemm_mma<<<dim3(2, MB), T, SMB>>>(BUF_X, DDIM, w_g0, b_g0,
        BUF_XG, EMB, BUF_NONE, 0, NNODES, EMB, 64, 1);
    // GCN layer 1 linear
    k_gemm_mma<<<dim3(2, MB), T, SMB>>>(BUF_XG, EMB, w_gcn1, nullptr,
        BUF_H, EMB, BUF_NONE, 0, NNODES, EMB, EMB, 0);

    // ---- join: gather needs CSR from s2
    cudaStreamWaitEvent(0, evB, 0);
    k_gather<<<(NNODES*32 + T-1)/T, T>>>(b_gcn1, BUF_XG, EMB, 0);

    // GCN layer 2
    k_gemm_mma<<<dim3(2, MB), T, SMB>>>(BUF_XG, EMB, w_gcn2, nullptr,
        BUF_H, EMB, BUF_NONE, 0, NNODES, EMB, EMB, 0);
    k_gather<<<(NNODES*32 + T-1)/T, T>>>(b_gcn2, BUF_X, DDIM, NH);

    // ---- fork: CrossNet overlaps the ResDNN GEMMs
    cudaEventRecord(evC, 0);
    cudaStreamWaitEvent(s2, evC, 0);
    k_cross<<<(NNODES*32 + T-1)/T, T, 0, s2>>>(cross_w, cross_b);
    cudaEventRecord(evD, s2);

    // ResDNN block 0
    k_gemm_mma<<<dim3(8, MB), T, SMB>>>(BUF_X, DDIM, res_w1, res_b1,
        BUF_H, RESHID, BUF_NONE, 0, NNODES, RESHID, DDIM, 1);
    k_gemm_mma<<<dim3(3, MB), T, SMB>>>(BUF_H, RESHID, res_w2, res_b2,
        BUF_XDEEP, DDIM, BUF_X, DDIM, NNODES, DDIM, RESHID, 1);

    // ResDNN block 1 (output into g_z[:, :192]; cross writes g_z[:, 192:])
    k_gemm_mma<<<dim3(8, MB), T, SMB>>>(BUF_XDEEP, DDIM, res_w1 + DDIM*RESHID, res_b1 + RESHID,
        BUF_H, RESHID, BUF_NONE, 0, NNODES, RESHID, DDIM, 1);
    k_gemm_mma<<<dim3(3, MB), T, SMB>>>(BUF_H, RESHID, res_w2 + RESHID*DDIM, res_b2 + DDIM,
        BUF_Z, ZDIM, BUF_XDEEP, DDIM, NNODES, DDIM, RESHID, 1);

    // ---- join: prediction needs cross's half of g_z
    cudaStreamWaitEvent(0, evD, 0);
    k_gemm_mma<<<dim3(5, MB), T, SMB>>>(BUF_Z, ZDIM, p_w1, p_b1,
        BUF_H, PREDH, BUF_NONE, 0, NNODES, PREDH, ZDIM, 1);
    k_pred2<<<(NNODES*32 + T-1)/T, T>>>(p_w2, p_b2, out);
}

// round 17
// speedup vs baseline: 1.0553x; 1.0553x over previous
#include <cuda_runtime.h>
#include <math.h>
#include <stdint.h>

// ---------------- problem constants ----------------
#define NNODES 50000
#define NEDGES 600000
#define NDISC  70
#define NH     64
#define EMB    128
#define DDIM   192
#define RESHID 512
#define PREDH  320
#define ZDIM   384
#define NBLK   49

// ---------------- device scratch ----------------
__device__ float g_dinv [NNODES];      // dinv during GCN; pred-dot accumulator afterwards
__device__ float g_x    [NNODES * DDIM];
__device__ float g_xg   [NNODES * EMB];
__device__ float g_h    [NNODES * RESHID];
__device__ float g_xdeep[NNODES * DDIM];
__device__ float g_z    [NNODES * ZDIM];
__device__ int   g_indeg [NNODES];
__device__ int   g_cursor[NNODES];
__device__ int   g_rowptr[NNODES + 1];
__device__ int   g_srcrow[NEDGES];
__device__ int   g_blksum[64];
__device__ int   g_blkoff[64];
__device__ float g_wt   [1114112];   // pre-split tf32 hi/lo weight planes

#define WT_G0    0
#define SZ_G0    8192
#define WT_GCN1  16384
#define SZ_GCN   16384
#define WT_GCN2  49152
#define WT_R1_0  81920
#define SZ_R1    98304
#define WT_R2_0  278528
#define SZ_R2    98304
#define WT_R1_1  475136
#define WT_R2_1  671744
#define WT_P1    868352
#define SZ_P1    122880

#define BUF_NONE  0
#define BUF_X     1
#define BUF_XG    2
#define BUF_H     3
#define BUF_XDEEP 4
#define BUF_Z     5

__device__ __forceinline__ float* bufptr(int id) {
    switch (id) {
        case BUF_X:     return g_x;
        case BUF_XG:    return g_xg;
        case BUF_H:     return g_h;
        case BUF_XDEEP: return g_xdeep;
        case BUF_Z:     return g_z;
        default:        return nullptr;
    }
}

__device__ __forceinline__ float leakyf(float v) { return v > 0.0f ? v : 0.01f * v; }

__device__ __forceinline__ uint32_t to_tf32(float f) {
    uint32_t r; asm("cvt.rna.tf32.f32 %0, %1;" : "=r"(r) : "f"(f)); return r;
}
__device__ __forceinline__ void split_tf32(float v, uint32_t& hi, uint32_t& lo) {
    hi = to_tf32(v);
    lo = to_tf32(v - __uint_as_float(hi));
}

__device__ __forceinline__ void mma_tf32(float* c, const uint32_t* a, const uint32_t* b) {
    asm volatile(
        "mma.sync.aligned.m16n8k8.row.col.f32.tf32.tf32.f32 "
        "{%0,%1,%2,%3}, {%4,%5,%6,%7}, {%8,%9}, {%0,%1,%2,%3};"
        : "+f"(c[0]), "+f"(c[1]), "+f"(c[2]), "+f"(c[3])
        : "r"(a[0]), "r"(a[1]), "r"(a[2]), "r"(a[3]), "r"(b[0]), "r"(b[1]));
}

// ---------------- graph prep ----------------
__global__ void k_zero_int() {
    int i = blockIdx.x * blockDim.x + threadIdx.x;
    if (i < NNODES) { g_indeg[i] = 0; g_cursor[i] = 0; }
}
__global__ void k_count(const int* __restrict__ col) {
    int e = blockIdx.x * blockDim.x + threadIdx.x;
    if (e < NEDGES) atomicAdd(&g_indeg[col[e]], 1);
}
__global__ void k_dinv() {
    int i = blockIdx.x * blockDim.x + threadIdx.x;
    if (i < NNODES) g_dinv[i] = rsqrtf((float)g_indeg[i] + 1.0f);
}
__global__ void __launch_bounds__(1024) k_scan1() {
    __shared__ int sh[32];
    int i = blockIdx.x * 1024 + threadIdx.x;
    int v = (i < NNODES) ? g_indeg[i] : 0;
    #pragma unroll
    for (int o = 16; o; o >>= 1) v += __shfl_xor_sync(~0u, v, o);
    if ((threadIdx.x & 31) == 0) sh[threadIdx.x >> 5] = v;
    __syncthreads();
    if (threadIdx.x < 32) {
        int t = sh[threadIdx.x];
        #pragma unroll
        for (int o = 16; o; o >>= 1) t += __shfl_xor_sync(~0u, t, o);
        if (threadIdx.x == 0) g_blksum[blockIdx.x] = t;
    }
}
__global__ void k_scan2() {
    if (threadIdx.x == 0) {
        int run = 0;
        for (int b = 0; b < NBLK; b++) { g_blkoff[b] = run; run += g_blksum[b]; }
        g_rowptr[NNODES] = run;
    }
}
__global__ void __launch_bounds__(1024) k_scan3() {
    __shared__ int wsum[32];
    int i = blockIdx.x * 1024 + threadIdx.x;
    int lane = threadIdx.x & 31, w = threadIdx.x >> 5;
    int v = (i < NNODES) ? g_indeg[i] : 0;
    int s = v;
    #pragma unroll
    for (int o = 1; o < 32; o <<= 1) {
        int t = __shfl_up_sync(~0u, s, o);
        if (lane >= o) s += t;
    }
    if (lane == 31) wsum[w] = s;
    __syncthreads();
    if (w == 0) {
        int t = wsum[lane];
        #pragma unroll
        for (int o = 1; o < 32; o <<= 1) {
            int u = __shfl_up_sync(~0u, t, o);
            if (lane >= o) t += u;
        }
        wsum[lane] = t;
    }
    __syncthreads();
    if (i < NNODES)
        g_rowptr[i] = s - v + (w > 0 ? wsum[w - 1] : 0) + g_blkoff[blockIdx.x];
}
__global__ void k_fill(const int* __restrict__ rows, const int* __restrict__ cols) {
    int e = blockIdx.x * blockDim.x + threadIdx.x;
    if (e < NEDGES) {
        int c = cols[e];
        int pos = g_rowptr[c] + atomicAdd(&g_cursor[c], 1);
        g_srcrow[pos] = rows[e];
    }
}

__global__ void k_cast(const int* __restrict__ disc) {
    int i = blockIdx.x * blockDim.x + threadIdx.x;
    if (i < NNODES * NH) {
        int m = i >> 6, c = i & 63;
        g_x[(size_t)m * DDIM + c] = (float)disc[(size_t)m * NDISC + c];
    }
}

__global__ void k_prep(const float* __restrict__ W, int off, int n) {
    int i = blockIdx.x * blockDim.x + threadIdx.x;
    if (i < n) {
        uint32_t h, l;
        split_tf32(W[i], h, l);
        g_wt[off + i]     = __uint_as_float(h);
        g_wt[off + n + i] = __uint_as_float(l);
    }
}

// zero pred accumulator (g_dinv reused; only after both gathers are done)
__global__ void k_zero_acc() {
    int i = blockIdx.x * blockDim.x + threadIdx.x;
    if (i < NNODES) g_dinv[i] = 0.0f;
}

// ---------------- fused GCN aggregate ----------------
__global__ void k_gather(const float* __restrict__ bias,
                         int dst_id, int dst_ld, int dst_off) {
    int node = (blockIdx.x * blockDim.x + threadIdx.x) >> 5;
    int lane = threadIdx.x & 31;
    if (node >= NNODES) return;
    float dc = g_dinv[node];
    int s = g_rowptr[node], e = g_rowptr[node + 1];
    float4 sum = make_float4(0.f, 0.f, 0.f, 0.f);
    for (int i = s; i < e; i++) {
        int r = g_srcrow[i];
        float nrm = g_dinv[r] * dc;
        float4 v = *(const float4*)(g_h + (size_t)r * EMB + lane * 4);
        sum.x = fmaf(v.x, nrm, sum.x);
        sum.y = fmaf(v.y, nrm, sum.y);
        sum.z = fmaf(v.z, nrm, sum.z);
        sum.w = fmaf(v.w, nrm, sum.w);
    }
    float4 hv = *(const float4*)(g_h + (size_t)node * EMB + lane * 4);
    float4 b4 = *(const float4*)(bias + lane * 4);
    float d2 = dc * dc;
    sum.x = leakyf(fmaf(hv.x, d2, sum.x) + b4.x);
    sum.y = leakyf(fmaf(hv.y, d2, sum.y) + b4.y);
    sum.z = leakyf(fmaf(hv.z, d2, sum.z) + b4.z);
    sum.w = leakyf(fmaf(hv.w, d2, sum.w) + b4.w);
    *(float4*)(bufptr(dst_id) + (size_t)node * dst_ld + dst_off + lane * 4) = sum;
}

// ---------------- 3xTF32 mma.sync GEMM (pre-split B; separate hi/lo planes) ----------------
// C[M,N] = act(A[M,K] @ W[K,N] + bias (+resid))
// If pw != nullptr (prediction mode): instead of writing C, each thread computes
// partial = sum_n leaky(v)*pw[n] over its columns, quad-reduces, atomicAdds into g_dinv.
// CTA tile 128(M) x 64(N); 8 warps (4m x 2n), warp tile 32x32; K-chunk 32.
#define AS_LD 36
#define BS_LD 72
#define A_TILE (128 * AS_LD)
#define B_TILE (32 * BS_LD)
#define SMEM_U32 (2 * A_TILE + 2 * B_TILE)

__global__ void __launch_bounds__(256) k_gemm_mma(
    int a_id, int lda,
    int woff, int wsize,
    const float* __restrict__ bias,
    int c_id, int ldc,
    int r_id, int ldr,
    int M, int N, int K, int act,
    const float* __restrict__ pw)
{
    extern __shared__ __align__(16) uint32_t sm[];
    uint32_t* AsH = sm;
    uint32_t* AsL = sm + A_TILE;
    uint32_t* BsH = sm + 2 * A_TILE;
    uint32_t* BsL = sm + 2 * A_TILE + B_TILE;

    const float* A  = bufptr(a_id);
    const float* Wh = g_wt + woff;
    const float* Wl = g_wt + woff + wsize;
    float* C = bufptr(c_id);
    const float* R = bufptr(r_id);

    int tid = threadIdx.x;
    int wid = tid >> 5, lane = tid & 31;
    int gid = lane >> 2, tig = lane & 3;
    int wm = wid & 3, wn = wid >> 2;

    int n0 = blockIdx.x * 64;
    int m0 = blockIdx.y * 128;

    int aq = tid & 7,  ar = tid >> 3;
    int bq = tid & 15, br = tid >> 4;

    float acc[2][4][4] = {};
    float4 pa[4], pbh[2], pbl[2];

    // prologue: chunk 0
    #pragma unroll
    for (int p = 0; p < 4; p++) {
        int ml = p * 32 + ar;
        pa[p] = make_float4(0.f, 0.f, 0.f, 0.f);
        if (m0 + ml < M)
            pa[p] = *(const float4*)(A + (size_t)(m0 + ml) * lda + aq * 4);
    }
    #pragma unroll
    for (int p = 0; p < 2; p++) {
        size_t bi = (size_t)(p * 16 + br) * N + n0 + bq * 4;
        pbh[p] = *(const float4*)(Wh + bi);
        pbl[p] = *(const float4*)(Wl + bi);
    }

    int nchunks = K >> 5;
    for (int kc = 0; kc < nchunks; kc++) {
        #pragma unroll
        for (int p = 0; p < 4; p++) {
            int ml = p * 32 + ar;
            uint32_t h0,l0,h1,l1,h2,l2,h3,l3;
            split_tf32(pa[p].x, h0, l0); split_tf32(pa[p].y, h1, l1);
            split_tf32(pa[p].z, h2, l2); split_tf32(pa[p].w, h3, l3);
            *(uint4*)&AsH[ml * AS_LD + aq * 4] = make_uint4(h0, h1, h2, h3);
            *(uint4*)&AsL[ml * AS_LD + aq * 4] = make_uint4(l0, l1, l2, l3);
        }
        #pragma unroll
        for (int p = 0; p < 2; p++) {
            int kr = p * 16 + br;
            *(float4*)&BsH[kr * BS_LD + bq * 4] = pbh[p];
            *(float4*)&BsL[kr * BS_LD + bq * 4] = pbl[p];
        }
        __syncthreads();

        if (kc + 1 < nchunks) {
            int k0n = (kc + 1) << 5;
            #pragma unroll
            for (int p = 0; p < 4; p++) {
                int ml = p * 32 + ar;
                pa[p] = make_float4(0.f, 0.f, 0.f, 0.f);
                if (m0 + ml < M)
                    pa[p] = *(const float4*)(A + (size_t)(m0 + ml) * lda + k0n + aq * 4);
            }
            #pragma unroll
            for (int p = 0; p < 2; p++) {
                size_t bi = (size_t)(k0n + p * 16 + br) * N + n0 + bq * 4;
                pbh[p] = *(const float4*)(Wh + bi);
                pbl[p] = *(const float4*)(Wl + bi);
            }
        }

        #pragma unroll
        for (int ks = 0; ks < 4; ks++) {
            int kl = ks * 8;
            uint32_t ah[2][4], al[2][4];
            #pragma unroll
            for (int mt = 0; mt < 2; mt++) {
                int row = wm * 32 + mt * 16 + gid;
                int i00 = (row    ) * AS_LD + kl + tig;
                int i10 = (row + 8) * AS_LD + kl + tig;
                ah[mt][0] = AsH[i00];     ah[mt][1] = AsH[i10];
                ah[mt][2] = AsH[i00 + 4]; ah[mt][3] = AsH[i10 + 4];
                al[mt][0] = AsL[i00];     al[mt][1] = AsL[i10];
                al[mt][2] = AsL[i00 + 4]; al[mt][3] = AsL[i10 + 4];
            }
            #pragma unroll
            for (int nt = 0; nt < 4; nt++) {
                int ncol = wn * 32 + nt * 8 + gid;
                uint32_t bh[2], bl[2];
                bh[0] = BsH[(kl + tig    ) * BS_LD + ncol];
                bh[1] = BsH[(kl + tig + 4) * BS_LD + ncol];
                bl[0] = BsL[(kl + tig    ) * BS_LD + ncol];
                bl[1] = BsL[(kl + tig + 4) * BS_LD + ncol];
                #pragma unroll
                for (int mt = 0; mt < 2; mt++) {
                    mma_tf32(acc[mt][nt], al[mt], bh);
                    mma_tf32(acc[mt][nt], ah[mt], bl);
                    mma_tf32(acc[mt][nt], ah[mt], bh);
                }
            }
        }
        __syncthreads();
    }

    if (pw == nullptr) {
        // normal epilogue
        #pragma unroll
        for (int mt = 0; mt < 2; mt++) {
            int row0 = m0 + wm * 32 + mt * 16 + gid;
            #pragma unroll
            for (int nt = 0; nt < 4; nt++) {
                int n = n0 + wn * 32 + nt * 8 + 2 * tig;
                float b0 = 0.f, b1 = 0.f;
                if (bias) { b0 = bias[n]; b1 = bias[n + 1]; }
                #pragma unroll
                for (int half = 0; half < 2; half++) {
                    int m = row0 + half * 8;
                    if (m < M) {
                        float v0 = acc[mt][nt][half * 2 + 0] + b0;
                        float v1 = acc[mt][nt][half * 2 + 1] + b1;
                        if (R) {
                            v0 += R[(size_t)m * ldr + n];
                            v1 += R[(size_t)m * ldr + n + 1];
                        }
                        if (act) { v0 = leakyf(v0); v1 = leakyf(v1); }
                        *(float2*)(C + (size_t)m * ldc + n) = make_float2(v0, v1);
                    }
                }
            }
        }
    } else {
        // fused prediction epilogue: partial = sum_n leaky(v + bias) * pw[n]
        float part[2][2] = {};
        #pragma unroll
        for (int mt = 0; mt < 2; mt++) {
            #pragma unroll
            for (int nt = 0; nt < 4; nt++) {
                int n = n0 + wn * 32 + nt * 8 + 2 * tig;
                float b0 = bias[n], b1 = bias[n + 1];
                float w0 = pw[n],   w1 = pw[n + 1];
                #pragma unroll
                for (int half = 0; half < 2; half++) {
                    float v0 = leakyf(acc[mt][nt][half * 2 + 0] + b0);
                    float v1 = leakyf(acc[mt][nt][half * 2 + 1] + b1);
                    part[mt][half] = fmaf(v0, w0, fmaf(v1, w1, part[mt][half]));
                }
            }
        }
        #pragma unroll
        for (int mt = 0; mt < 2; mt++) {
            #pragma unroll
            for (int half = 0; half < 2; half++) {
                float p = part[mt][half];
                p += __shfl_xor_sync(0xffffffffu, p, 1);
                p += __shfl_xor_sync(0xffffffffu, p, 2);
                if (tig == 0) {
                    int m = m0 + wm * 32 + mt * 16 + gid + half * 8;
                    if (m < M) atomicAdd(&g_dinv[m], p);
                }
            }
        }
    }
}

// ---------------- CrossNet ----------------
__global__ void k_cross(const float* __restrict__ cw, const float* __restrict__ cb) {
    int warp = (blockIdx.x * blockDim.x + threadIdx.x) >> 5;
    int lane = threadIdx.x & 31;
    if (warp >= NNODES) return;
    float x0[6], xc[6];
    #pragma unroll
    for (int j = 0; j < 6; j++) {
        x0[j] = g_x[(size_t)warp * DDIM + lane + 32 * j];
        xc[j] = x0[j];
    }
    #pragma unroll
    for (int l = 0; l < 2; l++) {
        float p = 0.0f;
        #pragma unroll
        for (int j = 0; j < 6; j++)
            p = fmaf(xc[j], cw[l * DDIM + lane + 32 * j], p);
        #pragma unroll
        for (int o = 16; o > 0; o >>= 1)
            p += __shfl_xor_sync(0xffffffffu, p, o);
        float xw = p;
        #pragma unroll
        for (int j = 0; j < 6; j++)
            xc[j] = fmaf(x0[j], xw, cb[l * DDIM + lane + 32 * j] + xc[j]);
    }
    #pragma unroll
    for (int j = 0; j < 6; j++)
        g_z[(size_t)warp * ZDIM + DDIM + lane + 32 * j] = xc[j];
}

// ---------------- final sigmoid ----------------
__global__ void k_sig(const float* __restrict__ b, float* __restrict__ out) {
    int i = blockIdx.x * blockDim.x + threadIdx.x;
    if (i < NNODES) {
        float v = g_dinv[i] + b[0];
        out[i] = 1.0f / (1.0f + expf(-v));
    }
}

// ---------------- launch (multi-stream fork/join) ----------------
extern "C" void kernel_launch(void* const* d_in, const int* in_sizes, int n_in,
                              void* d_out, int out_size) {
    const int* disc  = (const int*)d_in[0];
    const int* erow  = (const int*)d_in[1];
    const int* ecol  = erow + NEDGES;
    const float* w_g0   = (const float*)d_in[2];
    const float* b_g0   = (const float*)d_in[3];
    const float* w_gcn1 = (const float*)d_in[4];
    const float* b_gcn1 = (const float*)d_in[5];
    const float* w_gcn2 = (const float*)d_in[6];
    const float* b_gcn2 = (const float*)d_in[7];
    const float* res_w1 = (const float*)d_in[8];
    const float* res_b1 = (const float*)d_in[9];
    const float* res_w2 = (const float*)d_in[10];
    const float* res_b2 = (const float*)d_in[11];
    const float* cross_w = (const float*)d_in[12];
    const float* cross_b = (const float*)d_in[13];
    const float* p_w1 = (const float*)d_in[14];
    const float* p_b1 = (const float*)d_in[15];
    const float* p_w2 = (const float*)d_in[16];
    const float* p_b2 = (const float*)d_in[17];
    float* out = (float*)d_out;

    const int T = 256;
    const int MB = (NNODES + 127) / 128;   // 391
    const int SMB = SMEM_U32 * 4;

    static int inited = 0;
    static cudaStream_t s2;
    static cudaEvent_t evA, evB, evC, evD;
    if (!inited) {
        cudaFuncSetAttribute(k_gemm_mma, cudaFuncAttributeMaxDynamicSharedMemorySize, SMB);
        cudaStreamCreateWithFlags(&s2, cudaStreamNonBlocking);
        cudaEventCreateWithFlags(&evA, cudaEventDisableTiming);
        cudaEventCreateWithFlags(&evB, cudaEventDisableTiming);
        cudaEventCreateWithFlags(&evC, cudaEventDisableTiming);
        cudaEventCreateWithFlags(&evD, cudaEventDisableTiming);
        inited = 1;
    }

    // ---- main stream: inputs needed for the first two GEMMs
    k_cast<<<(NNODES*NH + T-1)/T, T>>>(disc);
    k_prep<<<(SZ_G0  + T-1)/T, T>>>(w_g0,   WT_G0,   SZ_G0);
    k_prep<<<(SZ_GCN + T-1)/T, T>>>(w_gcn1, WT_GCN1, SZ_GCN);

    // ---- fork: graph prep + remaining weight preps on s2
    cudaEventRecord(evA, 0);
    cudaStreamWaitEvent(s2, evA, 0);
    k_zero_int<<<(NNODES + T-1)/T, T, 0, s2>>>();
    k_count<<<(NEDGES + T-1)/T, T, 0, s2>>>(ecol);
    k_dinv<<<(NNODES + T-1)/T, T, 0, s2>>>();
    k_scan1<<<NBLK, 1024, 0, s2>>>();
    k_scan2<<<1, 32, 0, s2>>>();
    k_scan3<<<NBLK, 1024, 0, s2>>>();
    k_fill<<<(NEDGES + T-1)/T, T, 0, s2>>>(erow, ecol);
    k_prep<<<(SZ_GCN + T-1)/T, T, 0, s2>>>(w_gcn2, WT_GCN2, SZ_GCN);
    k_prep<<<(SZ_R1  + T-1)/T, T, 0, s2>>>(res_w1,         WT_R1_0, SZ_R1);
    k_prep<<<(SZ_R1  + T-1)/T, T, 0, s2>>>(res_w1 + SZ_R1, WT_R1_1, SZ_R1);
    k_prep<<<(SZ_R2  + T-1)/T, T, 0, s2>>>(res_w2,         WT_R2_0, SZ_R2);
    k_prep<<<(SZ_R2  + T-1)/T, T, 0, s2>>>(res_w2 + SZ_R2, WT_R2_1, SZ_R2);
    k_prep<<<(SZ_P1  + T-1)/T, T, 0, s2>>>(p_w1,   WT_P1,   SZ_P1);
    cudaEventRecord(evB, s2);

    // embed: xg = leaky(x_d @ w_g0 + b)   (overlaps s2)
    k_gemm_mma<<<dim3(2, MB), T, SMB>>>(BUF_X, DDIM, WT_G0, SZ_G0, b_g0,
        BUF_XG, EMB, BUF_NONE, 0, NNODES, EMB, 64, 1, nullptr);
    // GCN layer 1 linear (overlaps s2)
    k_gemm_mma<<<dim3(2, MB), T, SMB>>>(BUF_XG, EMB, WT_GCN1, SZ_GCN, nullptr,
        BUF_H, EMB, BUF_NONE, 0, NNODES, EMB, EMB, 0, nullptr);

    // ---- join: gather needs CSR (fill) from s2
    cudaStreamWaitEvent(0, evB, 0);
    k_gather<<<(NNODES*32 + T-1)/T, T>>>(b_gcn1, BUF_XG, EMB, 0);

    // GCN layer 2
    k_gemm_mma<<<dim3(2, MB), T, SMB>>>(BUF_XG, EMB, WT_GCN2, SZ_GCN, nullptr,
        BUF_H, EMB, BUF_NONE, 0, NNODES, EMB, EMB, 0, nullptr);
    k_gather<<<(NNODES*32 + T-1)/T, T>>>(b_gcn2, BUF_X, DDIM, NH);

    // ---- fork: CrossNet + pred-accumulator zero (g_dinv free after gathers)
    cudaEventRecord(evC, 0);
    cudaStreamWaitEvent(s2, evC, 0);
    k_cross<<<(NNODES*32 + T-1)/T, T, 0, s2>>>(cross_w, cross_b);
    k_zero_acc<<<(NNODES + T-1)/T, T, 0, s2>>>();
    cudaEventRecord(evD, s2);

    // ResDNN block 0
    k_gemm_mma<<<dim3(8, MB), T, SMB>>>(BUF_X, DDIM, WT_R1_0, SZ_R1, res_b1,
        BUF_H, RESHID, BUF_NONE, 0, NNODES, RESHID, DDIM, 1, nullptr);
    k_gemm_mma<<<dim3(3, MB), T, SMB>>>(BUF_H, RESHID, WT_R2_0, SZ_R2, res_b2,
        BUF_XDEEP, DDIM, BUF_X, DDIM, NNODES, DDIM, RESHID, 1, nullptr);

    // ResDNN block 1 (output into g_z[:, :192]; cross writes g_z[:, 192:])
    k_gemm_mma<<<dim3(8, MB), T, SMB>>>(BUF_XDEEP, DDIM, WT_R1_1, SZ_R1, res_b1 + RESHID,
        BUF_H, RESHID, BUF_NONE, 0, NNODES, RESHID, DDIM, 1, nullptr);
    k_gemm_mma<<<dim3(3, MB), T, SMB>>>(BUF_H, RESHID, WT_R2_1, SZ_R2, res_b2 + DDIM,
        BUF_Z, ZDIM, BUF_XDEEP, DDIM, NNODES, DDIM, RESHID, 1, nullptr);

    // ---- join: prediction needs cross's half of g_z and zeroed accumulator
    cudaStreamWaitEvent(0, evD, 0);
    // fused prediction GEMM: partial dot with p_w2 accumulated into g_dinv
    k_gemm_mma<<<dim3(5, MB), T, SMB>>>(BUF_Z, ZDIM, WT_P1, SZ_P1, p_b1,
        BUF_H, PREDH, BUF_NONE, 0, NNODES, PREDH, ZDIM, 1, p_w2);
    k_sig<<<(NNODES + T-1)/T, T>>>(p_b2, out);
}